// round 14
// baseline (speedup 1.0000x reference)
#include <cuda_runtime.h>
#include <cuda_bf16.h>
#include <cstdint>

// ---------------- device scratch (static allocation only) ----------------
__device__ float d_pw[4096 * 16];
__device__ float d_meanpart[4 * 8 * 128];
__device__ float d_win[4];
__device__ int   d_k;

__device__ __forceinline__ float gelu_erf(float v) {
    return 0.5f * v * (1.0f + erff(v * 0.70710678118654752440f));
}
__device__ __forceinline__ float sigmoidf(float v) {
    return 1.0f / (1.0f + expf(-v));
}

// ---------------- Kernel A: per-token selector + intensity ----------------
__global__ void __launch_bounds__(256) kA(
    const float* __restrict__ x, const float* __restrict__ ctx,
    const float* __restrict__ w1, const float* __restrict__ b1,
    const float* __restrict__ w2, const float* __restrict__ b2,
    const float* __restrict__ wi1, const float* __restrict__ bi1,
    const float* __restrict__ wi2, const float* __restrict__ bi2)
{
    extern __shared__ float sm[];
    float* ws1  = sm;
    float* ws2  = sm + 8192;
    float* wi1s = sm + 8704;
    float* cs   = sm + 25088;
    float* h1s  = sm + 27136;

    int tid = threadIdx.x;
    for (int i = tid; i < 2048; i += 256) ((float4*)ws1)[i]  = ((const float4*)w1)[i];
    for (int i = tid; i < 128;  i += 256) ((float4*)ws2)[i]  = ((const float4*)w2)[i];
    for (int i = tid; i < 4096; i += 256) ((float4*)wi1s)[i] = ((const float4*)wi1)[i];

    int w = tid >> 5, lane = tid & 31;
    int t = blockIdx.x * 8 + w;

    float4 xv = ((const float4*)x)[t * 32 + lane];
    float4 cv = ((const float4*)ctx)[t * 32 + lane];
    ((float4*)(cs + w * 256))[lane]       = xv;
    ((float4*)(cs + w * 256 + 128))[lane] = cv;
    __syncthreads();

    const float* c = cs + w * 256;

    float acc = b1[lane];
    #pragma unroll 8
    for (int i = 0; i < 256; i++) acc = fmaf(c[i], ws1[i * 32 + lane], acc);
    h1s[w * 32 + lane] = gelu_erf(acc);
    __syncwarp();

    float l = (lane < 16) ? b2[lane] : __int_as_float(0xff800000);
    if (lane < 16) {
        #pragma unroll
        for (int i = 0; i < 32; i++) l = fmaf(h1s[w * 32 + i], ws2[i * 16 + lane], l);
    }
    float m = l;
    #pragma unroll
    for (int off = 8; off >= 1; off >>= 1)
        m = fmaxf(m, __shfl_xor_sync(0xffffffffu, m, off));
    float e = (lane < 16) ? expf(l - m) : 0.0f;
    float s = e;
    #pragma unroll
    for (int off = 8; off >= 1; off >>= 1)
        s += __shfl_xor_sync(0xffffffffu, s, off);
    float pw = e / s;

    float a0 = bi1[lane], a1 = bi1[lane + 32];
    #pragma unroll 8
    for (int i = 0; i < 256; i++) {
        float ci = c[i];
        a0 = fmaf(ci, wi1s[i * 64 + lane], a0);
        a1 = fmaf(ci, wi1s[i * 64 + lane + 32], a1);
    }
    float part = gelu_erf(a0) * wi2[lane] + gelu_erf(a1) * wi2[lane + 32];
    #pragma unroll
    for (int off = 16; off >= 1; off >>= 1)
        part += __shfl_xor_sync(0xffffffffu, part, off);
    float inten = sigmoidf(part + bi2[0]);

    if (lane < 16) d_pw[t * 16 + lane] = pw * inten;
}

// ---------------- Kernel B1: partial batch means ----------------
__global__ void kB1(const float* __restrict__ x) {
    int b = blockIdx.x >> 3, chunk = blockIdx.x & 7;
    int d = threadIdx.x;
    const float* p = x + (size_t)(b * 1024 + chunk * 128) * 128 + d;
    float s = 0.0f;
    for (int i = 0; i < 128; i++) s += p[i * 128];
    d_meanpart[blockIdx.x * 128 + d] = s;
}

// ---------------- Kernel B2: per-batch window MLP (parallel) ----------------
// grid 4 (one per batch), block 256
__global__ void __launch_bounds__(256) kB2(
    const float* __restrict__ ww1, const float* __restrict__ bw1,
    const float* __restrict__ ww2, const float* __restrict__ bw2)
{
    __shared__ float mb[128];
    __shared__ float hsm[64];
    int b = blockIdx.x, tid = threadIdx.x;
    if (tid < 128) {
        float mv = 0.0f;
        for (int c = 0; c < 8; c++) mv += d_meanpart[(b * 8 + c) * 128 + tid];
        mb[tid] = mv * (1.0f / 1024.0f);
    }
    __syncthreads();
    // 64 hidden units, 4 threads each summing 32 inputs
    int j = tid >> 2, q = tid & 3;
    float a = 0.0f;
    #pragma unroll 8
    for (int i = 0; i < 32; i++) {
        int d = q * 32 + i;
        a = fmaf(mb[d], ww1[d * 64 + j], a);
    }
    a += __shfl_down_sync(0xffffffffu, a, 2);
    a += __shfl_down_sync(0xffffffffu, a, 1);
    if (q == 0) hsm[j] = gelu_erf(a + bw1[j]);
    __syncthreads();
    if (tid < 32) {
        float s = hsm[tid] * ww2[tid] + hsm[tid + 32] * ww2[tid + 32];
        #pragma unroll
        for (int off = 16; off >= 1; off >>= 1)
            s += __shfl_down_sync(0xffffffffu, s, off);
        if (tid == 0) d_win[b] = sigmoidf(s + bw2[0]) * 3840.0f + 256.0f;
    }
}

// ---------------- Kernel B3: global k ----------------
__global__ void kB3() {
    float winsum = d_win[0] + d_win[1] + d_win[2] + d_win[3];
    float spars = 0.1f * ((winsum * 0.25f) * (1.0f / 4096.0f));
    int k = (int)floorf(16384.0f * spars);
    if (k < 1) k = 1;
    d_k = k;
}

// ---------------- Kernel C: flow GEMM (64 tokens/CTA) ----------------
__global__ void __launch_bounds__(256) kC(const float* __restrict__ pat,
                                          float* __restrict__ out, int tok_off)
{
    __shared__ unsigned long long pwp[1024];
    int tid = threadIdx.x;
    int t0 = tok_off + blockIdx.x * 64;
    int col0 = blockIdx.y * 1024 + tid * 4;

    const ulonglong2* p2 = (const ulonglong2*)pat;
    unsigned long long pa[16], pb[16];
    #pragma unroll
    for (int p = 0; p < 16; p++) {
        ulonglong2 v = p2[(p * 16384 + col0) >> 2];
        pa[p] = v.x; pb[p] = v.y;
    }

    for (int i = tid; i < 1024; i += 256) {
        unsigned int b = __float_as_uint(d_pw[t0 * 16 + i]);
        pwp[i] = ((unsigned long long)b << 32) | (unsigned long long)b;
    }
    __syncthreads();

    ulonglong2* o2 = (ulonglong2*)out;
    #pragma unroll 4
    for (int t = 0; t < 64; ++t) {
        unsigned long long a0 = 0ULL, a1 = 0ULL;
        const unsigned long long* pwt = &pwp[t * 16];
        #pragma unroll
        for (int p = 0; p < 16; p++) {
            unsigned long long wv = pwt[p];
            asm("fma.rn.f32x2 %0, %1, %2, %3;" : "=l"(a0) : "l"(pa[p]), "l"(wv), "l"(a0));
            asm("fma.rn.f32x2 %0, %1, %2, %3;" : "=l"(a1) : "l"(pb[p]), "l"(wv), "l"(a1));
        }
        ulonglong2 r; r.x = a0; r.y = a1;
        o2[((size_t)(t0 + t) * 16384 + col0) >> 2] = r;
    }
}

// ---------------- kD helper: top-rank bin selection (256-thread block) ----------------
__device__ __forceinline__ void selbin(unsigned int* hist, unsigned int* csum,
                                       unsigned int* s_sel, unsigned int* s_rem,
                                       int nb, int tid)
{
    int nchunk = nb / 8;   // 256 or 128
    if (tid < nchunk) {
        unsigned int cs = 0;
        #pragma unroll
        for (int j = 0; j < 8; j++) cs += hist[tid * 8 + j];
        csum[tid] = cs;
    }
    __syncthreads();
    int per = nchunk / 32;
    if (tid < 32) {
        unsigned int ws = 0;
        for (int j = 0; j < per; j++) ws += csum[tid * per + j];
        unsigned int sfx = ws;
        #pragma unroll
        for (int off = 1; off <= 16; off <<= 1) {
            unsigned int t2 = __shfl_down_sync(0xffffffffu, sfx, off);
            if (tid + off < 32) sfx += t2;
        }
        unsigned int rem_t = *s_rem;
        unsigned int bal = __ballot_sync(0xffffffffu, sfx >= rem_t);
        int J = 31 - __clz((int)bal);
        if (tid == J) {
            unsigned int rem = rem_t - (sfx - ws);
            int chunk = J * per;
            for (int cix = J * per + per - 1; cix >= J * per; --cix) {
                unsigned int cc = csum[cix];
                if (rem <= cc) { chunk = cix; break; }
                rem -= cc;
            }
            int bin = chunk * 8;
            for (int bix = chunk * 8 + 7; bix >= chunk * 8; --bix) {
                unsigned int hc = hist[bix];
                if (rem <= hc) { bin = bix; break; }
                rem -= hc;
            }
            *s_sel = (unsigned int)bin;
            *s_rem = rem;
        }
    }
    __syncthreads();
}

// ---------------- Kernel D: exact top-k mask ----------------
// grid 1024 (1 token), block 256 (8 warps) -> 8 CTAs/SM, single wave.
__global__ void __launch_bounds__(256) kD(float* __restrict__ out, int tok_off)
{
    __shared__ unsigned int hist[2048];
    __shared__ unsigned int cand[4096];   // 8 warps x 512 slots
    __shared__ unsigned int csum[256];
    __shared__ unsigned int wcnt[8];
    __shared__ unsigned int s_sel, s_rem, s_bad;

    int tid = threadIdx.x;
    int warp = tid >> 5;
    int lane = tid & 31;
    unsigned int lt = (1u << lane) - 1u;
    float* rowp = out + (size_t)(tok_off + blockIdx.x) * 16384;
    float4* g4 = (float4*)rowp;

    for (int i = tid; i < 2048; i += 256) hist[i] = 0u;
    if (tid == 0) s_bad = 0u;
    __syncthreads();

    // ---- phase 0a: 1024 samples (4/thread), top-11-bit histogram ----
    unsigned int sk[4];
    #pragma unroll
    for (int j = 0; j < 4; j++) {
        sk[j] = __float_as_uint(rowp[tid + j * 4096]) & 0x7fffffffu;
        atomicAdd(&hist[sk[j] >> 21], 1u);
    }
    if (tid == 0) s_rem = 192u;   // sample rank -> ~3K expected survivors
    __syncthreads();
    selbin(hist, csum, &s_sel, &s_rem, 2048, tid);
    unsigned int b0 = s_sel;
    __syncthreads();

    // ---- phase 0b: refine bound, bits 20..10 within bin b0 ----
    for (int i = tid; i < 2048; i += 256) hist[i] = 0u;
    __syncthreads();
    #pragma unroll
    for (int j = 0; j < 4; j++)
        if ((sk[j] >> 21) == b0) atomicAdd(&hist[(sk[j] >> 10) & 2047u], 1u);
    __syncthreads();
    selbin(hist, csum, &s_sel, &s_rem, 2048, tid);
    unsigned int bound = (b0 << 21) | (s_sel << 10);   // 22-bit conservative bound
    __syncthreads();

    unsigned int kk = (unsigned int)d_k;
    for (int i = tid; i < 2048; i += 256) hist[i] = 0u;
    __syncthreads();

    // ---- phase 1: warp-local compaction (no atomics, no shuffles) ----
    // warp w owns elements [w*2048, (w+1)*2048), survivors -> cand[w*512..]
    {
        unsigned int base = 0;
        const float4* wseg = g4 + warp * 512;
        #pragma unroll
        for (int i = 0; i < 16; i++) {
            float4 v = wseg[lane + i * 32];
            unsigned int ks[4] = {__float_as_uint(v.x) & 0x7fffffffu, __float_as_uint(v.y) & 0x7fffffffu,
                                  __float_as_uint(v.z) & 0x7fffffffu, __float_as_uint(v.w) & 0x7fffffffu};
            #pragma unroll
            for (int j = 0; j < 4; j++) {
                bool pred = ks[j] >= bound;
                unsigned int mask = __ballot_sync(0xffffffffu, pred);
                if (pred) {
                    unsigned int pos = base + __popc(mask & lt);
                    if (pos < 512u) cand[warp * 512 + pos] = ks[j];
                }
                base += (unsigned int)__popc(mask);
            }
        }
        if (lane == 0) {
            wcnt[warp] = base;
            if (base > 512u) atomicOr(&s_bad, 1u);
        }
    }
    __syncthreads();

    unsigned int cnt = 0;
    #pragma unroll
    for (int w2 = 0; w2 < 8; w2++) cnt += wcnt[w2];
    unsigned int thrkey;

    if (!s_bad && cnt >= kk) {
        // ---- phase 2: exact 3-level selection over candidates ----
        if (tid == 0) s_rem = kk;
        __syncthreads();
        for (int j = tid; j < 4096; j += 256) {
            unsigned int w2 = j >> 9, i2 = j & 511u;
            if (i2 < wcnt[w2]) atomicAdd(&hist[cand[j] >> 21], 1u);
        }
        __syncthreads();
        selbin(hist, csum, &s_sel, &s_rem, 2048, tid);
        unsigned int sel0 = s_sel;
        __syncthreads();

        for (int i = tid; i < 2048; i += 256) hist[i] = 0u;
        __syncthreads();
        for (int j = tid; j < 4096; j += 256) {
            unsigned int w2 = j >> 9, i2 = j & 511u;
            if (i2 < wcnt[w2]) {
                unsigned int key = cand[j];
                if ((key >> 21) == sel0) atomicAdd(&hist[(key >> 10) & 2047u], 1u);
            }
        }
        __syncthreads();
        selbin(hist, csum, &s_sel, &s_rem, 2048, tid);
        unsigned int p21 = (sel0 << 11) | s_sel;
        __syncthreads();

        for (int i = tid; i < 1024; i += 256) hist[i] = 0u;
        __syncthreads();
        for (int j = tid; j < 4096; j += 256) {
            unsigned int w2 = j >> 9, i2 = j & 511u;
            if (i2 < wcnt[w2]) {
                unsigned int key = cand[j];
                if ((key >> 10) == p21) atomicAdd(&hist[key & 1023u], 1u);
            }
        }
        __syncthreads();
        selbin(hist, csum, &s_sel, &s_rem, 1024, tid);
        thrkey = (p21 << 10) | s_sel;
    } else {
        // ---- fallback: exact 3-level full-row refinement (rare) ----
        for (int i = tid; i < 2048; i += 256) hist[i] = 0u;
        if (tid == 0) s_rem = kk;
        __syncthreads();
        #pragma unroll
        for (int i = 0; i < 16; i++) {
            float4 v = g4[tid + i * 256];
            atomicAdd(&hist[(__float_as_uint(v.x) & 0x7fffffffu) >> 21], 1u);
            atomicAdd(&hist[(__float_as_uint(v.y) & 0x7fffffffu) >> 21], 1u);
            atomicAdd(&hist[(__float_as_uint(v.z) & 0x7fffffffu) >> 21], 1u);
            atomicAdd(&hist[(__float_as_uint(v.w) & 0x7fffffffu) >> 21], 1u);
        }
        __syncthreads();
        selbin(hist, csum, &s_sel, &s_rem, 2048, tid);
        unsigned int sel0 = s_sel;
        __syncthreads();

        for (int i = tid; i < 2048; i += 256) hist[i] = 0u;
        __syncthreads();
        #pragma unroll
        for (int i = 0; i < 16; i++) {
            float4 v = g4[tid + i * 256];
            float vals[4] = {v.x, v.y, v.z, v.w};
            #pragma unroll
            for (int j = 0; j < 4; j++) {
                unsigned int key = __float_as_uint(vals[j]) & 0x7fffffffu;
                if ((key >> 21) == sel0) atomicAdd(&hist[(key >> 10) & 2047u], 1u);
            }
        }
        __syncthreads();
        selbin(hist, csum, &s_sel, &s_rem, 2048, tid);
        unsigned int p21 = (sel0 << 11) | s_sel;
        __syncthreads();

        for (int i = tid; i < 1024; i += 256) hist[i] = 0u;
        __syncthreads();
        #pragma unroll
        for (int i = 0; i < 16; i++) {
            float4 v = g4[tid + i * 256];
            float vals[4] = {v.x, v.y, v.z, v.w};
            #pragma unroll
            for (int j = 0; j < 4; j++) {
                unsigned int key = __float_as_uint(vals[j]) & 0x7fffffffu;
                if ((key >> 10) == p21) atomicAdd(&hist[key & 1023u], 1u);
            }
        }
        __syncthreads();
        selbin(hist, csum, &s_sel, &s_rem, 1024, tid);
        thrkey = (p21 << 10) | s_sel;
    }

    // ---- mask + write (L2-hot re-read) ----
    #pragma unroll
    for (int i = 0; i < 16; i++) {
        float4 w = g4[tid + i * 256];
        w.x = ((__float_as_uint(w.x) & 0x7fffffffu) >= thrkey) ? w.x : 0.0f;
        w.y = ((__float_as_uint(w.y) & 0x7fffffffu) >= thrkey) ? w.y : 0.0f;
        w.z = ((__float_as_uint(w.z) & 0x7fffffffu) >= thrkey) ? w.z : 0.0f;
        w.w = ((__float_as_uint(w.w) & 0x7fffffffu) >= thrkey) ? w.w : 0.0f;
        g4[tid + i * 256] = w;
    }
}

// ---------------- launch ----------------
extern "C" void kernel_launch(void* const* d_in, const int* in_sizes, int n_in,
                              void* d_out, int out_size)
{
    const float* x    = (const float*)d_in[0];
    const float* ctx  = (const float*)d_in[1];
    const float* pat  = (const float*)d_in[2];
    const float* w1   = (const float*)d_in[3];
    const float* b1   = (const float*)d_in[4];
    const float* w2   = (const float*)d_in[5];
    const float* b2   = (const float*)d_in[6];
    const float* wi1  = (const float*)d_in[7];
    const float* bi1  = (const float*)d_in[8];
    const float* wi2  = (const float*)d_in[9];
    const float* bi2  = (const float*)d_in[10];
    const float* ww1  = (const float*)d_in[11];
    const float* bw1  = (const float*)d_in[12];
    const float* ww2  = (const float*)d_in[13];
    const float* bw2  = (const float*)d_in[14];
    float* out = (float*)d_out;

    cudaFuncSetAttribute(kA, cudaFuncAttributeMaxDynamicSharedMemorySize, 109568);

    kA<<<512, 256, 109568>>>(x, ctx, w1, b1, w2, b2, wi1, bi1, wi2, bi2);
    kB1<<<32, 128>>>(x);
    kB2<<<4, 256>>>(ww1, bw1, ww2, bw2);
    kB3<<<1, 1>>>();

    // interleaved per stripe: stripe's 64MB stays L2-resident between kC and kD
    // (kD of stripe 0 is launch #6 -> captured by ncu -s 5 -c 1)
    for (int s = 0; s < 4; s++) {
        dim3 gC(16, 16);
        kC<<<gC, 256>>>(pat, out, s * 1024);
        kD<<<1024, 256>>>(out, s * 1024);
    }
}

// round 15
// speedup vs baseline: 1.1408x; 1.1408x over previous
#include <cuda_runtime.h>
#include <cuda_bf16.h>
#include <cstdint>

// ---------------- device scratch (static allocation only) ----------------
__device__ float d_pw[4096 * 16];
__device__ float d_meanpart[4 * 8 * 128];
__device__ int   d_k;
__device__ int   d_cnt;   // kB last-block counter (self-resetting)

__device__ __forceinline__ float gelu_erf(float v) {
    return 0.5f * v * (1.0f + erff(v * 0.70710678118654752440f));
}
__device__ __forceinline__ float sigmoidf(float v) {
    return 1.0f / (1.0f + expf(-v));
}

// ---------------- Kernel A: per-token selector + intensity ----------------
__global__ void __launch_bounds__(256) kA(
    const float* __restrict__ x, const float* __restrict__ ctx,
    const float* __restrict__ w1, const float* __restrict__ b1,
    const float* __restrict__ w2, const float* __restrict__ b2,
    const float* __restrict__ wi1, const float* __restrict__ bi1,
    const float* __restrict__ wi2, const float* __restrict__ bi2)
{
    extern __shared__ float sm[];
    float* ws1  = sm;
    float* ws2  = sm + 8192;
    float* wi1s = sm + 8704;
    float* cs   = sm + 25088;
    float* h1s  = sm + 27136;

    int tid = threadIdx.x;
    for (int i = tid; i < 2048; i += 256) ((float4*)ws1)[i]  = ((const float4*)w1)[i];
    for (int i = tid; i < 128;  i += 256) ((float4*)ws2)[i]  = ((const float4*)w2)[i];
    for (int i = tid; i < 4096; i += 256) ((float4*)wi1s)[i] = ((const float4*)wi1)[i];

    int w = tid >> 5, lane = tid & 31;
    int t = blockIdx.x * 8 + w;

    float4 xv = ((const float4*)x)[t * 32 + lane];
    float4 cv = ((const float4*)ctx)[t * 32 + lane];
    ((float4*)(cs + w * 256))[lane]       = xv;
    ((float4*)(cs + w * 256 + 128))[lane] = cv;
    __syncthreads();

    const float* c = cs + w * 256;

    float acc = b1[lane];
    #pragma unroll 8
    for (int i = 0; i < 256; i++) acc = fmaf(c[i], ws1[i * 32 + lane], acc);
    h1s[w * 32 + lane] = gelu_erf(acc);
    __syncwarp();

    float l = (lane < 16) ? b2[lane] : __int_as_float(0xff800000);
    if (lane < 16) {
        #pragma unroll
        for (int i = 0; i < 32; i++) l = fmaf(h1s[w * 32 + i], ws2[i * 16 + lane], l);
    }
    float m = l;
    #pragma unroll
    for (int off = 8; off >= 1; off >>= 1)
        m = fmaxf(m, __shfl_xor_sync(0xffffffffu, m, off));
    float e = (lane < 16) ? expf(l - m) : 0.0f;
    float s = e;
    #pragma unroll
    for (int off = 8; off >= 1; off >>= 1)
        s += __shfl_xor_sync(0xffffffffu, s, off);
    float pw = e / s;

    float a0 = bi1[lane], a1 = bi1[lane + 32];
    #pragma unroll 8
    for (int i = 0; i < 256; i++) {
        float ci = c[i];
        a0 = fmaf(ci, wi1s[i * 64 + lane], a0);
        a1 = fmaf(ci, wi1s[i * 64 + lane + 32], a1);
    }
    float part = gelu_erf(a0) * wi2[lane] + gelu_erf(a1) * wi2[lane + 32];
    #pragma unroll
    for (int off = 16; off >= 1; off >>= 1)
        part += __shfl_xor_sync(0xffffffffu, part, off);
    float inten = sigmoidf(part + bi2[0]);

    if (lane < 16) d_pw[t * 16 + lane] = pw * inten;
}

// ---------------- Kernel B: batch means + window MLP + k (fused) ----------------
// grid 32, block 128. Last finishing block runs the MLP for all 4 batches.
__global__ void __launch_bounds__(128) kB(
    const float* __restrict__ x,
    const float* __restrict__ ww1, const float* __restrict__ bw1,
    const float* __restrict__ ww2, const float* __restrict__ bw2)
{
    int tid = threadIdx.x;
    {
        int b = blockIdx.x >> 3, chunk = blockIdx.x & 7;
        const float* p = x + (size_t)(b * 1024 + chunk * 128) * 128 + tid;
        float s = 0.0f;
        for (int i = 0; i < 128; i++) s += p[i * 128];
        d_meanpart[blockIdx.x * 128 + tid] = s;
    }
    __threadfence();
    __syncthreads();
    __shared__ int amLast;
    if (tid == 0) amLast = (atomicAdd(&d_cnt, 1) == 31);
    __syncthreads();
    if (!amLast) return;

    __threadfence();
    __shared__ float mb[128];
    __shared__ float hsm[64];
    float winsum = 0.0f;
    for (int b = 0; b < 4; b++) {
        float mv = 0.0f;
        #pragma unroll
        for (int c = 0; c < 8; c++) mv += d_meanpart[(b * 8 + c) * 128 + tid];
        mb[tid] = mv * (1.0f / 1024.0f);
        __syncthreads();
        // hidden: j = tid>>1 (64 units), q = tid&1 sums 64 inputs each
        int j = tid >> 1, q = tid & 1;
        float a = 0.0f;
        #pragma unroll 8
        for (int i = 0; i < 64; i++) {
            int d = q * 64 + i;
            a = fmaf(mb[d], ww1[d * 64 + j], a);
        }
        a += __shfl_down_sync(0xffffffffu, a, 1);
        if (q == 0) hsm[j] = gelu_erf(a + bw1[j]);
        __syncthreads();
        if (tid < 32) {
            float s2 = hsm[tid] * ww2[tid] + hsm[tid + 32] * ww2[tid + 32];
            #pragma unroll
            for (int off = 16; off >= 1; off >>= 1)
                s2 += __shfl_down_sync(0xffffffffu, s2, off);
            if (tid == 0) winsum += sigmoidf(s2 + bw2[0]) * 3840.0f + 256.0f;
        }
        __syncthreads();
    }
    if (tid == 0) {
        float spars = 0.1f * ((winsum * 0.25f) * (1.0f / 4096.0f));
        int k = (int)floorf(16384.0f * spars);
        if (k < 1) k = 1;
        d_k = k;
        d_cnt = 0;   // reset for next graph replay
    }
}

// ---------------- Kernel C: flow GEMM (64 tokens/CTA) ----------------
__global__ void __launch_bounds__(256) kC(const float* __restrict__ pat,
                                          float* __restrict__ out, int tok_off)
{
    __shared__ unsigned long long pwp[1024];
    int tid = threadIdx.x;
    int t0 = tok_off + blockIdx.x * 64;
    int col0 = blockIdx.y * 1024 + tid * 4;

    const ulonglong2* p2 = (const ulonglong2*)pat;
    unsigned long long pa[16], pb[16];
    #pragma unroll
    for (int p = 0; p < 16; p++) {
        ulonglong2 v = p2[(p * 16384 + col0) >> 2];
        pa[p] = v.x; pb[p] = v.y;
    }

    for (int i = tid; i < 1024; i += 256) {
        unsigned int b = __float_as_uint(d_pw[t0 * 16 + i]);
        pwp[i] = ((unsigned long long)b << 32) | (unsigned long long)b;
    }
    __syncthreads();

    ulonglong2* o2 = (ulonglong2*)out;
    #pragma unroll 4
    for (int t = 0; t < 64; ++t) {
        unsigned long long a0 = 0ULL, a1 = 0ULL;
        const unsigned long long* pwt = &pwp[t * 16];
        #pragma unroll
        for (int p = 0; p < 16; p++) {
            unsigned long long wv = pwt[p];
            asm("fma.rn.f32x2 %0, %1, %2, %3;" : "=l"(a0) : "l"(pa[p]), "l"(wv), "l"(a0));
            asm("fma.rn.f32x2 %0, %1, %2, %3;" : "=l"(a1) : "l"(pb[p]), "l"(wv), "l"(a1));
        }
        ulonglong2 r; r.x = a0; r.y = a1;
        o2[((size_t)(t0 + t) * 16384 + col0) >> 2] = r;
    }
}

// ---------------- kD helper: top-rank bin selection ----------------
__device__ __forceinline__ void selbin(unsigned int* hist, unsigned int* csum,
                                       unsigned int* s_sel, unsigned int* s_rem,
                                       int nb, int tid)
{
    int nchunk = nb / 8;
    if (tid < nchunk) {
        unsigned int cs = 0;
        #pragma unroll
        for (int j = 0; j < 8; j++) cs += hist[tid * 8 + j];
        csum[tid] = cs;
    }
    __syncthreads();
    int per = nchunk / 32;
    if (tid < 32) {
        unsigned int ws = 0;
        for (int j = 0; j < per; j++) ws += csum[tid * per + j];
        unsigned int sfx = ws;
        #pragma unroll
        for (int off = 1; off <= 16; off <<= 1) {
            unsigned int t2 = __shfl_down_sync(0xffffffffu, sfx, off);
            if (tid + off < 32) sfx += t2;
        }
        unsigned int rem_t = *s_rem;
        unsigned int bal = __ballot_sync(0xffffffffu, sfx >= rem_t);
        int J = 31 - __clz((int)bal);
        if (tid == J) {
            unsigned int rem = rem_t - (sfx - ws);
            int chunk = J * per;
            for (int cix = J * per + per - 1; cix >= J * per; --cix) {
                unsigned int cc = csum[cix];
                if (rem <= cc) { chunk = cix; break; }
                rem -= cc;
            }
            int bin = chunk * 8;
            for (int bix = chunk * 8 + 7; bix >= chunk * 8; --bix) {
                unsigned int hc = hist[bix];
                if (rem <= hc) { bin = bix; break; }
                rem -= hc;
            }
            *s_sel = (unsigned int)bin;
            *s_rem = rem;
        }
    }
    __syncthreads();
}

// ---------------- Kernel D: exact top-k mask ----------------
// grid 1024 (1 token), block 512 (16 warps). Warp-local atomic-free compaction.
__global__ void __launch_bounds__(512) kD(float* __restrict__ out, int tok_off)
{
    __shared__ unsigned int hist[2048];
    __shared__ unsigned int cand[4096];   // 16 warps x 256 slots
    __shared__ unsigned int csum[256];
    __shared__ unsigned int wcnt[16];
    __shared__ unsigned int s_sel, s_rem, s_bad;

    int tid = threadIdx.x;
    int warp = tid >> 5;
    int lane = tid & 31;
    unsigned int lt = (1u << lane) - 1u;
    float* rowp = out + (size_t)(tok_off + blockIdx.x) * 16384;
    float4* g4 = (float4*)rowp;

    for (int i = tid; i < 2048; i += 512) hist[i] = 0u;
    if (tid == 0) s_bad = 0u;
    __syncthreads();

    // ---- phase 0a: 1024 samples, top-11-bit histogram ----
    int sblk = (tid >> 8) * 8192;
    int soff = tid & 255;
    unsigned int k0 = __float_as_uint(rowp[sblk + soff]) & 0x7fffffffu;
    unsigned int k1 = __float_as_uint(rowp[sblk + 4096 + soff]) & 0x7fffffffu;
    atomicAdd(&hist[k0 >> 21], 1u);
    atomicAdd(&hist[k1 >> 21], 1u);
    if (tid == 0) s_rem = 192u;
    __syncthreads();
    selbin(hist, csum, &s_sel, &s_rem, 2048, tid);
    unsigned int b0 = s_sel;
    __syncthreads();

    // ---- phase 0b: refine bound, bits 20..10 within bin b0 ----
    for (int i = tid; i < 2048; i += 512) hist[i] = 0u;
    __syncthreads();
    if ((k0 >> 21) == b0) atomicAdd(&hist[(k0 >> 10) & 2047u], 1u);
    if ((k1 >> 21) == b0) atomicAdd(&hist[(k1 >> 10) & 2047u], 1u);
    __syncthreads();
    selbin(hist, csum, &s_sel, &s_rem, 2048, tid);
    unsigned int bound = (b0 << 21) | (s_sel << 10);
    __syncthreads();

    unsigned int kk = (unsigned int)d_k;
    for (int i = tid; i < 2048; i += 512) hist[i] = 0u;
    __syncthreads();

    // ---- phase 1: warp-local compaction, loads batched ahead (MLP=8) ----
    {
        unsigned int base = 0;
        const float4* wseg = g4 + warp * 256;
        float4 v[8];
        #pragma unroll
        for (int i = 0; i < 8; i++) v[i] = wseg[lane + i * 32];
        #pragma unroll
        for (int i = 0; i < 8; i++) {
            unsigned int ks[4] = {__float_as_uint(v[i].x) & 0x7fffffffu, __float_as_uint(v[i].y) & 0x7fffffffu,
                                  __float_as_uint(v[i].z) & 0x7fffffffu, __float_as_uint(v[i].w) & 0x7fffffffu};
            #pragma unroll
            for (int j = 0; j < 4; j++) {
                bool pred = ks[j] >= bound;
                unsigned int mask = __ballot_sync(0xffffffffu, pred);
                if (pred) {
                    unsigned int pos = base + __popc(mask & lt);
                    if (pos < 256u) cand[warp * 256 + pos] = ks[j];
                }
                base += (unsigned int)__popc(mask);
            }
        }
        if (lane == 0) {
            wcnt[warp] = base;
            if (base > 256u) atomicOr(&s_bad, 1u);
        }
    }
    __syncthreads();

    unsigned int cnt = 0;
    #pragma unroll
    for (int w2 = 0; w2 < 16; w2++) cnt += wcnt[w2];
    unsigned int thrkey;

    if (!s_bad && cnt >= kk) {
        // ---- phase 2: exact 3-level selection over candidates ----
        if (tid == 0) s_rem = kk;
        __syncthreads();
        for (int j = tid; j < 4096; j += 512) {
            unsigned int w2 = j >> 8, i2 = j & 255u;
            if (i2 < wcnt[w2]) atomicAdd(&hist[cand[j] >> 21], 1u);
        }
        __syncthreads();
        selbin(hist, csum, &s_sel, &s_rem, 2048, tid);
        unsigned int sel0 = s_sel;
        __syncthreads();

        for (int i = tid; i < 2048; i += 512) hist[i] = 0u;
        __syncthreads();
        for (int j = tid; j < 4096; j += 512) {
            unsigned int w2 = j >> 8, i2 = j & 255u;
            if (i2 < wcnt[w2]) {
                unsigned int key = cand[j];
                if ((key >> 21) == sel0) atomicAdd(&hist[(key >> 10) & 2047u], 1u);
            }
        }
        __syncthreads();
        selbin(hist, csum, &s_sel, &s_rem, 2048, tid);
        unsigned int p21 = (sel0 << 11) | s_sel;
        __syncthreads();

        for (int i = tid; i < 1024; i += 512) hist[i] = 0u;
        __syncthreads();
        for (int j = tid; j < 4096; j += 512) {
            unsigned int w2 = j >> 8, i2 = j & 255u;
            if (i2 < wcnt[w2]) {
                unsigned int key = cand[j];
                if ((key >> 10) == p21) atomicAdd(&hist[key & 1023u], 1u);
            }
        }
        __syncthreads();
        selbin(hist, csum, &s_sel, &s_rem, 1024, tid);
        thrkey = (p21 << 10) | s_sel;
    } else {
        // ---- fallback: exact 3-level full-row refinement (rare) ----
        for (int i = tid; i < 2048; i += 512) hist[i] = 0u;
        if (tid == 0) s_rem = kk;
        __syncthreads();
        #pragma unroll
        for (int i = 0; i < 8; i++) {
            float4 v = g4[tid + i * 512];
            atomicAdd(&hist[(__float_as_uint(v.x) & 0x7fffffffu) >> 21], 1u);
            atomicAdd(&hist[(__float_as_uint(v.y) & 0x7fffffffu) >> 21], 1u);
            atomicAdd(&hist[(__float_as_uint(v.z) & 0x7fffffffu) >> 21], 1u);
            atomicAdd(&hist[(__float_as_uint(v.w) & 0x7fffffffu) >> 21], 1u);
        }
        __syncthreads();
        selbin(hist, csum, &s_sel, &s_rem, 2048, tid);
        unsigned int sel0 = s_sel;
        __syncthreads();

        for (int i = tid; i < 2048; i += 512) hist[i] = 0u;
        __syncthreads();
        #pragma unroll
        for (int i = 0; i < 8; i++) {
            float4 v = g4[tid + i * 512];
            float vals[4] = {v.x, v.y, v.z, v.w};
            #pragma unroll
            for (int j = 0; j < 4; j++) {
                unsigned int key = __float_as_uint(vals[j]) & 0x7fffffffu;
                if ((key >> 21) == sel0) atomicAdd(&hist[(key >> 10) & 2047u], 1u);
            }
        }
        __syncthreads();
        selbin(hist, csum, &s_sel, &s_rem, 2048, tid);
        unsigned int p21 = (sel0 << 11) | s_sel;
        __syncthreads();

        for (int i = tid; i < 1024; i += 512) hist[i] = 0u;
        __syncthreads();
        #pragma unroll
        for (int i = 0; i < 8; i++) {
            float4 v = g4[tid + i * 512];
            float vals[4] = {v.x, v.y, v.z, v.w};
            #pragma unroll
            for (int j = 0; j < 4; j++) {
                unsigned int key = __float_as_uint(vals[j]) & 0x7fffffffu;
                if ((key >> 10) == p21) atomicAdd(&hist[key & 1023u], 1u);
            }
        }
        __syncthreads();
        selbin(hist, csum, &s_sel, &s_rem, 1024, tid);
        thrkey = (p21 << 10) | s_sel;
    }

    // ---- mask + write, loads batched ahead ----
    {
        float4 v[8];
        #pragma unroll
        for (int i = 0; i < 8; i++) v[i] = g4[tid + i * 512];
        #pragma unroll
        for (int i = 0; i < 8; i++) {
            float4 w = v[i];
            w.x = ((__float_as_uint(w.x) & 0x7fffffffu) >= thrkey) ? w.x : 0.0f;
            w.y = ((__float_as_uint(w.y) & 0x7fffffffu) >= thrkey) ? w.y : 0.0f;
            w.z = ((__float_as_uint(w.z) & 0x7fffffffu) >= thrkey) ? w.z : 0.0f;
            w.w = ((__float_as_uint(w.w) & 0x7fffffffu) >= thrkey) ? w.w : 0.0f;
            g4[tid + i * 512] = w;
        }
    }
}

// ---------------- launch ----------------
extern "C" void kernel_launch(void* const* d_in, const int* in_sizes, int n_in,
                              void* d_out, int out_size)
{
    const float* x    = (const float*)d_in[0];
    const float* ctx  = (const float*)d_in[1];
    const float* pat  = (const float*)d_in[2];
    const float* w1   = (const float*)d_in[3];
    const float* b1   = (const float*)d_in[4];
    const float* w2   = (const float*)d_in[5];
    const float* b2   = (const float*)d_in[6];
    const float* wi1  = (const float*)d_in[7];
    const float* bi1  = (const float*)d_in[8];
    const float* wi2  = (const float*)d_in[9];
    const float* bi2  = (const float*)d_in[10];
    const float* ww1  = (const float*)d_in[11];
    const float* bw1  = (const float*)d_in[12];
    const float* ww2  = (const float*)d_in[13];
    const float* bw2  = (const float*)d_in[14];
    float* out = (float*)d_out;

    cudaFuncSetAttribute(kA, cudaFuncAttributeMaxDynamicSharedMemorySize, 109568);

    kA<<<512, 256, 109568>>>(x, ctx, w1, b1, w2, b2, wi1, bi1, wi2, bi2);   // idx 0
    kB<<<32, 128>>>(x, ww1, bw1, ww2, bw2);                                  // idx 1

    // interleaved per stripe; kD0 lands at launch index 3 for ncu capture
    for (int s = 0; s < 4; s++) {
        dim3 gC(16, 16);
        kC<<<gC, 256>>>(pat, out, s * 1024);
        kD<<<1024, 512>>>(out, s * 1024);
    }
}

// round 16
// speedup vs baseline: 1.1632x; 1.0196x over previous
#include <cuda_runtime.h>
#include <cuda_bf16.h>
#include <cstdint>

// ---------------- device scratch (static allocation only) ----------------
__device__ float d_pw[4096 * 16];
__device__ float d_meanpart[4 * 8 * 128];
__device__ int   d_k;
__device__ int   d_cnt;   // kB last-block counter (self-resetting)

__device__ __forceinline__ float gelu_erf(float v) {
    return 0.5f * v * (1.0f + erff(v * 0.70710678118654752440f));
}
__device__ __forceinline__ float sigmoidf(float v) {
    return 1.0f / (1.0f + expf(-v));
}

// ---------------- Kernel A: per-token selector + intensity ----------------
__global__ void __launch_bounds__(256) kA(
    const float* __restrict__ x, const float* __restrict__ ctx,
    const float* __restrict__ w1, const float* __restrict__ b1,
    const float* __restrict__ w2, const float* __restrict__ b2,
    const float* __restrict__ wi1, const float* __restrict__ bi1,
    const float* __restrict__ wi2, const float* __restrict__ bi2)
{
    extern __shared__ float sm[];
    float* ws1  = sm;
    float* ws2  = sm + 8192;
    float* wi1s = sm + 8704;
    float* cs   = sm + 25088;
    float* h1s  = sm + 27136;

    int tid = threadIdx.x;
    for (int i = tid; i < 2048; i += 256) ((float4*)ws1)[i]  = ((const float4*)w1)[i];
    for (int i = tid; i < 128;  i += 256) ((float4*)ws2)[i]  = ((const float4*)w2)[i];
    for (int i = tid; i < 4096; i += 256) ((float4*)wi1s)[i] = ((const float4*)wi1)[i];

    int w = tid >> 5, lane = tid & 31;
    int t = blockIdx.x * 8 + w;

    float4 xv = ((const float4*)x)[t * 32 + lane];
    float4 cv = ((const float4*)ctx)[t * 32 + lane];
    ((float4*)(cs + w * 256))[lane]       = xv;
    ((float4*)(cs + w * 256 + 128))[lane] = cv;
    __syncthreads();

    const float* c = cs + w * 256;

    float acc = b1[lane];
    #pragma unroll 8
    for (int i = 0; i < 256; i++) acc = fmaf(c[i], ws1[i * 32 + lane], acc);
    h1s[w * 32 + lane] = gelu_erf(acc);
    __syncwarp();

    float l = (lane < 16) ? b2[lane] : __int_as_float(0xff800000);
    if (lane < 16) {
        #pragma unroll
        for (int i = 0; i < 32; i++) l = fmaf(h1s[w * 32 + i], ws2[i * 16 + lane], l);
    }
    float m = l;
    #pragma unroll
    for (int off = 8; off >= 1; off >>= 1)
        m = fmaxf(m, __shfl_xor_sync(0xffffffffu, m, off));
    float e = (lane < 16) ? expf(l - m) : 0.0f;
    float s = e;
    #pragma unroll
    for (int off = 8; off >= 1; off >>= 1)
        s += __shfl_xor_sync(0xffffffffu, s, off);
    float pw = e / s;

    float a0 = bi1[lane], a1 = bi1[lane + 32];
    #pragma unroll 8
    for (int i = 0; i < 256; i++) {
        float ci = c[i];
        a0 = fmaf(ci, wi1s[i * 64 + lane], a0);
        a1 = fmaf(ci, wi1s[i * 64 + lane + 32], a1);
    }
    float part = gelu_erf(a0) * wi2[lane] + gelu_erf(a1) * wi2[lane + 32];
    #pragma unroll
    for (int off = 16; off >= 1; off >>= 1)
        part += __shfl_xor_sync(0xffffffffu, part, off);
    float inten = sigmoidf(part + bi2[0]);

    if (lane < 16) d_pw[t * 16 + lane] = pw * inten;
}

// ---------------- Kernel B: batch means + window MLP + k (fused) ----------------
__global__ void __launch_bounds__(128) kB(
    const float* __restrict__ x,
    const float* __restrict__ ww1, const float* __restrict__ bw1,
    const float* __restrict__ ww2, const float* __restrict__ bw2)
{
    int tid = threadIdx.x;
    {
        int b = blockIdx.x >> 3, chunk = blockIdx.x & 7;
        const float* p = x + (size_t)(b * 1024 + chunk * 128) * 128 + tid;
        float s = 0.0f;
        for (int i = 0; i < 128; i++) s += p[i * 128];
        d_meanpart[blockIdx.x * 128 + tid] = s;
    }
    __threadfence();
    __syncthreads();
    __shared__ int amLast;
    if (tid == 0) amLast = (atomicAdd(&d_cnt, 1) == 31);
    __syncthreads();
    if (!amLast) return;

    __threadfence();
    __shared__ float mb[128];
    __shared__ float hsm[64];
    float winsum = 0.0f;
    for (int b = 0; b < 4; b++) {
        float mv = 0.0f;
        #pragma unroll
        for (int c = 0; c < 8; c++) mv += d_meanpart[(b * 8 + c) * 128 + tid];
        mb[tid] = mv * (1.0f / 1024.0f);
        __syncthreads();
        int j = tid >> 1, q = tid & 1;
        float a = 0.0f;
        #pragma unroll 8
        for (int i = 0; i < 64; i++) {
            int d = q * 64 + i;
            a = fmaf(mb[d], ww1[d * 64 + j], a);
        }
        a += __shfl_down_sync(0xffffffffu, a, 1);
        if (q == 0) hsm[j] = gelu_erf(a + bw1[j]);
        __syncthreads();
        if (tid < 32) {
            float s2 = hsm[tid] * ww2[tid] + hsm[tid + 32] * ww2[tid + 32];
            #pragma unroll
            for (int off = 16; off >= 1; off >>= 1)
                s2 += __shfl_down_sync(0xffffffffu, s2, off);
            if (tid == 0) winsum += sigmoidf(s2 + bw2[0]) * 3840.0f + 256.0f;
        }
        __syncthreads();
    }
    if (tid == 0) {
        float spars = 0.1f * ((winsum * 0.25f) * (1.0f / 4096.0f));
        int k = (int)floorf(16384.0f * spars);
        if (k < 1) k = 1;
        d_k = k;
        d_cnt = 0;
    }
}

// ---------------- Kernel C: flow GEMM (64 tokens/CTA) ----------------
__global__ void __launch_bounds__(256) kC(const float* __restrict__ pat,
                                          float* __restrict__ out, int tok_off)
{
    __shared__ unsigned long long pwp[1024];
    int tid = threadIdx.x;
    int t0 = tok_off + blockIdx.x * 64;
    int col0 = blockIdx.y * 1024 + tid * 4;

    const ulonglong2* p2 = (const ulonglong2*)pat;
    unsigned long long pa[16], pb[16];
    #pragma unroll
    for (int p = 0; p < 16; p++) {
        ulonglong2 v = p2[(p * 16384 + col0) >> 2];
        pa[p] = v.x; pb[p] = v.y;
    }

    for (int i = tid; i < 1024; i += 256) {
        unsigned int b = __float_as_uint(d_pw[t0 * 16 + i]);
        pwp[i] = ((unsigned long long)b << 32) | (unsigned long long)b;
    }
    __syncthreads();

    ulonglong2* o2 = (ulonglong2*)out;
    #pragma unroll 4
    for (int t = 0; t < 64; ++t) {
        unsigned long long a0 = 0ULL, a1 = 0ULL;
        const unsigned long long* pwt = &pwp[t * 16];
        #pragma unroll
        for (int p = 0; p < 16; p++) {
            unsigned long long wv = pwt[p];
            asm("fma.rn.f32x2 %0, %1, %2, %3;" : "=l"(a0) : "l"(pa[p]), "l"(wv), "l"(a0));
            asm("fma.rn.f32x2 %0, %1, %2, %3;" : "=l"(a1) : "l"(pb[p]), "l"(wv), "l"(a1));
        }
        ulonglong2 r; r.x = a0; r.y = a1;
        o2[((size_t)(t0 + t) * 16384 + col0) >> 2] = r;
    }
}

// ---------------- kD helper: top-rank bin selection ----------------
__device__ __forceinline__ void selbin(unsigned int* hist, unsigned int* csum,
                                       unsigned int* s_sel, unsigned int* s_rem,
                                       int nb, int tid)
{
    int nchunk = nb / 8;
    if (tid < nchunk) {
        unsigned int cs = 0;
        #pragma unroll
        for (int j = 0; j < 8; j++) cs += hist[tid * 8 + j];
        csum[tid] = cs;
    }
    __syncthreads();
    int per = nchunk / 32;
    if (tid < 32) {
        unsigned int ws = 0;
        for (int j = 0; j < per; j++) ws += csum[tid * per + j];
        unsigned int sfx = ws;
        #pragma unroll
        for (int off = 1; off <= 16; off <<= 1) {
            unsigned int t2 = __shfl_down_sync(0xffffffffu, sfx, off);
            if (tid + off < 32) sfx += t2;
        }
        unsigned int rem_t = *s_rem;
        unsigned int bal = __ballot_sync(0xffffffffu, sfx >= rem_t);
        int J = 31 - __clz((int)bal);
        if (tid == J) {
            unsigned int rem = rem_t - (sfx - ws);
            int chunk = J * per;
            for (int cix = J * per + per - 1; cix >= J * per; --cix) {
                unsigned int cc = csum[cix];
                if (rem <= cc) { chunk = cix; break; }
                rem -= cc;
            }
            int bin = chunk * 8;
            for (int bix = chunk * 8 + 7; bix >= chunk * 8; --bix) {
                unsigned int hc = hist[bix];
                if (rem <= hc) { bin = bix; break; }
                rem -= hc;
            }
            *s_sel = (unsigned int)bin;
            *s_rem = rem;
        }
    }
    __syncthreads();
}

// ---------------- Kernel D: exact top-k mask ----------------
// grid 1024 (1 token), block 512 (16 warps). Scan-based compaction, no ballots.
__global__ void __launch_bounds__(512) kD(float* __restrict__ out, int tok_off)
{
    __shared__ unsigned int hist[2048];
    __shared__ unsigned int cand[4096];   // 16 warps x 256 slots
    __shared__ unsigned int csum[256];
    __shared__ unsigned int wcnt[16];
    __shared__ unsigned int s_sel, s_rem, s_bad;

    int tid = threadIdx.x;
    int warp = tid >> 5;
    int lane = tid & 31;
    float* rowp = out + (size_t)(tok_off + blockIdx.x) * 16384;
    float4* g4 = (float4*)rowp;
    const uint4 z4 = make_uint4(0u, 0u, 0u, 0u);

    ((uint4*)hist)[tid]; // no-op silencer
    ((uint4*)hist)[tid < 512 ? tid : 0] = z4;   // zero all 2048 bins (512x16B)
    if (tid == 0) s_bad = 0u;
    __syncthreads();

    // ---- phase 0a: 1024 samples, top-11-bit histogram ----
    int sblk = (tid >> 8) * 8192;
    int soff = tid & 255;
    unsigned int k0 = __float_as_uint(rowp[sblk + soff]) & 0x7fffffffu;
    unsigned int k1 = __float_as_uint(rowp[sblk + 4096 + soff]) & 0x7fffffffu;
    atomicAdd(&hist[k0 >> 21], 1u);
    atomicAdd(&hist[k1 >> 21], 1u);
    if (tid == 0) s_rem = 192u;
    __syncthreads();
    selbin(hist, csum, &s_sel, &s_rem, 2048, tid);
    unsigned int b0 = s_sel;
    __syncthreads();

    // ---- phase 0b: refine bound, bits 20..10 within bin b0 ----
    ((uint4*)hist)[tid] = z4;
    __syncthreads();
    if ((k0 >> 21) == b0) atomicAdd(&hist[(k0 >> 10) & 2047u], 1u);
    if ((k1 >> 21) == b0) atomicAdd(&hist[(k1 >> 10) & 2047u], 1u);
    __syncthreads();
    selbin(hist, csum, &s_sel, &s_rem, 2048, tid);
    unsigned int bound = (b0 << 21) | (s_sel << 10);
    __syncthreads();

    unsigned int kk = (unsigned int)d_k;
    ((uint4*)hist)[tid] = z4;
    __syncthreads();

    // ---- phase 1: scan-based warp-local compaction (no per-element ballots) ----
    {
        const float4* wseg = g4 + warp * 256;
        // pass A: count survivors per thread (pipelined ALU)
        unsigned int cnt_t = 0;
        #pragma unroll
        for (int i = 0; i < 8; i++) {
            float4 v = wseg[lane + i * 32];
            cnt_t += ((__float_as_uint(v.x) & 0x7fffffffu) >= bound);
            cnt_t += ((__float_as_uint(v.y) & 0x7fffffffu) >= bound);
            cnt_t += ((__float_as_uint(v.z) & 0x7fffffffu) >= bound);
            cnt_t += ((__float_as_uint(v.w) & 0x7fffffffu) >= bound);
        }
        // warp inclusive scan -> exclusive offset
        unsigned int pre = cnt_t;
        #pragma unroll
        for (int off = 1; off <= 16; off <<= 1) {
            unsigned int u = __shfl_up_sync(0xffffffffu, pre, off);
            if (lane >= off) pre += u;
        }
        unsigned int excl = pre - cnt_t;
        unsigned int total = __shfl_sync(0xffffffffu, pre, 31);
        // pass B: re-read (L1-hot) and write survivors to private range
        unsigned int pos = warp * 256u + excl;
        unsigned int lim = warp * 256u + 256u;
        #pragma unroll
        for (int i = 0; i < 8; i++) {
            float4 v = wseg[lane + i * 32];
            unsigned int ks[4] = {__float_as_uint(v.x) & 0x7fffffffu, __float_as_uint(v.y) & 0x7fffffffu,
                                  __float_as_uint(v.z) & 0x7fffffffu, __float_as_uint(v.w) & 0x7fffffffu};
            #pragma unroll
            for (int j = 0; j < 4; j++) {
                if (ks[j] >= bound) {
                    if (pos < lim) cand[pos] = ks[j];
                    pos++;
                }
            }
        }
        if (lane == 0) {
            wcnt[warp] = total;
            if (total > 256u) atomicOr(&s_bad, 1u);
        }
    }
    __syncthreads();

    unsigned int cnt = 0;
    #pragma unroll
    for (int w2 = 0; w2 < 16; w2++) cnt += wcnt[w2];
    unsigned int thrkey;

    if (!s_bad && cnt >= kk) {
        // ---- phase 2: exact 3-level selection over candidates ----
        if (tid == 0) s_rem = kk;
        __syncthreads();
        for (int j = tid; j < 4096; j += 512) {
            unsigned int w2 = j >> 8, i2 = j & 255u;
            if (i2 < wcnt[w2]) atomicAdd(&hist[cand[j] >> 21], 1u);
        }
        __syncthreads();
        selbin(hist, csum, &s_sel, &s_rem, 2048, tid);
        unsigned int sel0 = s_sel;
        __syncthreads();

        ((uint4*)hist)[tid] = z4;
        __syncthreads();
        for (int j = tid; j < 4096; j += 512) {
            unsigned int w2 = j >> 8, i2 = j & 255u;
            if (i2 < wcnt[w2]) {
                unsigned int key = cand[j];
                if ((key >> 21) == sel0) atomicAdd(&hist[(key >> 10) & 2047u], 1u);
            }
        }
        __syncthreads();
        selbin(hist, csum, &s_sel, &s_rem, 2048, tid);
        unsigned int p21 = (sel0 << 11) | s_sel;
        __syncthreads();

        if (tid < 256) ((uint4*)hist)[tid] = z4;
        __syncthreads();
        for (int j = tid; j < 4096; j += 512) {
            unsigned int w2 = j >> 8, i2 = j & 255u;
            if (i2 < wcnt[w2]) {
                unsigned int key = cand[j];
                if ((key >> 10) == p21) atomicAdd(&hist[key & 1023u], 1u);
            }
        }
        __syncthreads();
        selbin(hist, csum, &s_sel, &s_rem, 1024, tid);
        thrkey = (p21 << 10) | s_sel;
    } else {
        // ---- fallback: exact 3-level full-row refinement (rare) ----
        ((uint4*)hist)[tid] = z4;
        if (tid == 0) s_rem = kk;
        __syncthreads();
        #pragma unroll
        for (int i = 0; i < 8; i++) {
            float4 v = g4[tid + i * 512];
            atomicAdd(&hist[(__float_as_uint(v.x) & 0x7fffffffu) >> 21], 1u);
            atomicAdd(&hist[(__float_as_uint(v.y) & 0x7fffffffu) >> 21], 1u);
            atomicAdd(&hist[(__float_as_uint(v.z) & 0x7fffffffu) >> 21], 1u);
            atomicAdd(&hist[(__float_as_uint(v.w) & 0x7fffffffu) >> 21], 1u);
        }
        __syncthreads();
        selbin(hist, csum, &s_sel, &s_rem, 2048, tid);
        unsigned int sel0 = s_sel;
        __syncthreads();

        ((uint4*)hist)[tid] = z4;
        __syncthreads();
        #pragma unroll
        for (int i = 0; i < 8; i++) {
            float4 v = g4[tid + i * 512];
            float vals[4] = {v.x, v.y, v.z, v.w};
            #pragma unroll
            for (int j = 0; j < 4; j++) {
                unsigned int key = __float_as_uint(vals[j]) & 0x7fffffffu;
                if ((key >> 21) == sel0) atomicAdd(&hist[(key >> 10) & 2047u], 1u);
            }
        }
        __syncthreads();
        selbin(hist, csum, &s_sel, &s_rem, 2048, tid);
        unsigned int p21 = (sel0 << 11) | s_sel;
        __syncthreads();

        if (tid < 256) ((uint4*)hist)[tid] = z4;
        __syncthreads();
        #pragma unroll
        for (int i = 0; i < 8; i++) {
            float4 v = g4[tid + i * 512];
            float vals[4] = {v.x, v.y, v.z, v.w};
            #pragma unroll
            for (int j = 0; j < 4; j++) {
                unsigned int key = __float_as_uint(vals[j]) & 0x7fffffffu;
                if ((key >> 10) == p21) atomicAdd(&hist[key & 1023u], 1u);
            }
        }
        __syncthreads();
        selbin(hist, csum, &s_sel, &s_rem, 1024, tid);
        thrkey = (p21 << 10) | s_sel;
    }

    // ---- mask + write, loads batched ahead ----
    {
        float4 v[8];
        #pragma unroll
        for (int i = 0; i < 8; i++) v[i] = g4[tid + i * 512];
        #pragma unroll
        for (int i = 0; i < 8; i++) {
            float4 w = v[i];
            w.x = ((__float_as_uint(w.x) & 0x7fffffffu) >= thrkey) ? w.x : 0.0f;
            w.y = ((__float_as_uint(w.y) & 0x7fffffffu) >= thrkey) ? w.y : 0.0f;
            w.z = ((__float_as_uint(w.z) & 0x7fffffffu) >= thrkey) ? w.z : 0.0f;
            w.w = ((__float_as_uint(w.w) & 0x7fffffffu) >= thrkey) ? w.w : 0.0f;
            g4[tid + i * 512] = w;
        }
    }
}

// ---------------- launch ----------------
extern "C" void kernel_launch(void* const* d_in, const int* in_sizes, int n_in,
                              void* d_out, int out_size)
{
    const float* x    = (const float*)d_in[0];
    const float* ctx  = (const float*)d_in[1];
    const float* pat  = (const float*)d_in[2];
    const float* w1   = (const float*)d_in[3];
    const float* b1   = (const float*)d_in[4];
    const float* w2   = (const float*)d_in[5];
    const float* b2   = (const float*)d_in[6];
    const float* wi1  = (const float*)d_in[7];
    const float* bi1  = (const float*)d_in[8];
    const float* wi2  = (const float*)d_in[9];
    const float* bi2  = (const float*)d_in[10];
    const float* ww1  = (const float*)d_in[11];
    const float* bw1  = (const float*)d_in[12];
    const float* ww2  = (const float*)d_in[13];
    const float* bw2  = (const float*)d_in[14];
    float* out = (float*)d_out;

    cudaFuncSetAttribute(kA, cudaFuncAttributeMaxDynamicSharedMemorySize, 109568);

    kA<<<512, 256, 109568>>>(x, ctx, w1, b1, w2, b2, wi1, bi1, wi2, bi2);   // idx 0
    kB<<<32, 128>>>(x, ww1, bw1, ww2, bw2);                                  // idx 1

    // interleaved per stripe; kD0 lands at launch index 3 for ncu capture
    for (int s = 0; s < 4; s++) {
        dim3 gC(16, 16);
        kC<<<gC, 256>>>(pat, out, s * 1024);
        kD<<<1024, 512>>>(out, s * 1024);
    }
}